// round 3
// baseline (speedup 1.0000x reference)
#include <cuda_runtime.h>
#include <math.h>

// Problem constants
#define T_TOK 2048
#define H_DIM 1024
#define E_EXP 32
#define I_DIM 2048

// Tile config
#define BM 128
#define BN 128
#define BK 16
#define NTHREADS 256
#define MAX_TILES 64

// -------- scratch (static device globals; no runtime allocation) --------
__device__ float g_mix[T_TOK * 96];                  // router qkv mix
__device__ float g_topw[T_TOK * 2];                  // per-token top2 softmax weights
__device__ int   g_counts[E_EXP];                    // tokens per expert
__device__ int   g_list[E_EXP * T_TOK];              // pair codes (t*2+slot) grouped by expert
__device__ int   g_tile_e[MAX_TILES];
__device__ int   g_tile_m0[MAX_TILES];
__device__ int   g_ntiles;
__device__ float g_gu  [(size_t)T_TOK * 2 * 2 * I_DIM]; // raw gate/up GEMM output (64 MB)
__device__ float g_act [(size_t)T_TOK * 2 * I_DIM];     // SwiGLU activations      (32 MB)
__device__ float g_outp[(size_t)T_TOK * 2 * H_DIM];     // per-pair FFN output     (16 MB)

// ------------------------------------------------------------------
__global__ void zero_counts_kernel() {
    if (threadIdx.x < E_EXP) g_counts[threadIdx.x] = 0;
}

// ------------------------------------------------------------------
// mix = x @ wqkv^T   [2048, 96], K=1024 (small, simple 64x64x16 / 4x4)
__global__ __launch_bounds__(256) void mix_gemm_kernel(
    const float* __restrict__ x, const float* __restrict__ wqkv)
{
    __shared__ float As[16][64];
    __shared__ float Bs[16][64];
    const int N = 96, K = H_DIM;
    int m0 = blockIdx.y * 64, n0 = blockIdx.x * 64;
    int tid = threadIdx.x;
    int tx = tid & 15, ty = tid >> 4;
    int lm = tid >> 2, lk = (tid & 3) * 4;

    const float* Arow = x + (size_t)(m0 + lm) * K;
    int brow = n0 + lm;
    const float* Brow = wqkv + (size_t)min(brow, N - 1) * K;
    bool bvalid = brow < N;

    float acc[4][4] = {};
    for (int k0 = 0; k0 < K; k0 += 16) {
        float4 av = *(const float4*)(Arow + k0 + lk);
        float4 bv = bvalid ? *(const float4*)(Brow + k0 + lk) : make_float4(0.f,0.f,0.f,0.f);
        As[lk+0][lm]=av.x; As[lk+1][lm]=av.y; As[lk+2][lm]=av.z; As[lk+3][lm]=av.w;
        Bs[lk+0][lm]=bv.x; Bs[lk+1][lm]=bv.y; Bs[lk+2][lm]=bv.z; Bs[lk+3][lm]=bv.w;
        __syncthreads();
        #pragma unroll
        for (int kk = 0; kk < 16; kk++) {
            float4 a = *(const float4*)&As[kk][ty*4];
            float4 b = *(const float4*)&Bs[kk][tx*4];
            float ar[4] = {a.x,a.y,a.z,a.w};
            float br[4] = {b.x,b.y,b.z,b.w};
            #pragma unroll
            for (int i = 0; i < 4; i++)
                #pragma unroll
                for (int j = 0; j < 4; j++)
                    acc[i][j] += ar[i] * br[j];
        }
        __syncthreads();
    }
    #pragma unroll
    for (int i = 0; i < 4; i++) {
        int m = m0 + ty*4 + i;
        #pragma unroll
        for (int j = 0; j < 4; j++) {
            int n = n0 + tx*4 + j;
            if (n < N) g_mix[(size_t)m * 96 + n] = acc[i][j];
        }
    }
}

// ------------------------------------------------------------------
// Router: per-token softmax-attention over experts, top-2, weights, lists.
__global__ void route_kernel()
{
    int t = blockIdx.x * 4 + (threadIdx.x >> 5);
    int lane = threadIdx.x & 31;
    if (t >= T_TOK) return;
    const float* mix = g_mix + (size_t)t * 96;
    float q  = mix[lane];
    float kf = mix[32 + lane];
    float vf = mix[64 + lane];

    float m = -INFINITY;
    #pragma unroll
    for (int f = 0; f < 32; f++) {
        float kk = __shfl_sync(0xffffffffu, kf, f);
        m = fmaxf(m, q * kk);
    }
    float s = 0.f, num = 0.f;
    #pragma unroll
    for (int f = 0; f < 32; f++) {
        float kk = __shfl_sync(0xffffffffu, kf, f);
        float vv = __shfl_sync(0xffffffffu, vf, f);
        float p = expf(q * kk - m);
        s += p; num += p * vv;
    }
    float logit = num / s;

    float v1 = logit; int i1 = lane;
    #pragma unroll
    for (int off = 16; off > 0; off >>= 1) {
        float ov = __shfl_xor_sync(0xffffffffu, v1, off);
        int   oi = __shfl_xor_sync(0xffffffffu, i1, off);
        if (ov > v1 || (ov == v1 && oi < i1)) { v1 = ov; i1 = oi; }
    }
    float mval = (lane == i1) ? -INFINITY : logit;
    float v2 = mval; int i2 = lane;
    #pragma unroll
    for (int off = 16; off > 0; off >>= 1) {
        float ov = __shfl_xor_sync(0xffffffffu, v2, off);
        int   oi = __shfl_xor_sync(0xffffffffu, i2, off);
        if (ov > v2 || (ov == v2 && oi < i2)) { v2 = ov; i2 = oi; }
    }

    if (lane == 0) {
        float e2 = expf(v2 - v1);
        float inv = 1.f / (1.f + e2);
        g_topw[t*2 + 0] = inv;
        g_topw[t*2 + 1] = e2 * inv;
        int p1 = atomicAdd(&g_counts[i1], 1);
        g_list[i1 * T_TOK + p1] = t*2 + 0;
        int p2 = atomicAdd(&g_counts[i2], 1);
        g_list[i2 * T_TOK + p2] = t*2 + 1;
    }
}

// ------------------------------------------------------------------
// Build compact (expert, m0) tile worklist.
__global__ void build_tiles_kernel()
{
    int e = threadIdx.x;   // 32 threads
    int ne = g_counts[e];
    int ct = (ne + BM - 1) / BM;
    int pre = ct;
    #pragma unroll
    for (int off = 1; off < 32; off <<= 1) {
        int v = __shfl_up_sync(0xffffffffu, pre, off);
        if (e >= off) pre += v;
    }
    int start = pre - ct;
    for (int i = 0; i < ct; i++) {
        g_tile_e[start + i]  = e;
        g_tile_m0[start + i] = i * BM;
    }
    if (e == 31) g_ntiles = pre;
}

// ------------------------------------------------------------------
// Gathered GEMM. MODE 1: g_gu[code,:] = x[code>>1,:] @ ws_e^T  (K=1024, N=4096)
//                MODE 2: g_outp[code,:] = g_act[code,:] @ w2_e^T (K=2048, N=1024)
// All scratch referenced as device globals (NOT host-passed).
template<int MODE>
__global__ __launch_bounds__(NTHREADS, 2) void moe_gemm_kernel(
    const float* __restrict__ Ain, const float* __restrict__ W)
{
    constexpr int KDIM = (MODE == 1) ? H_DIM : I_DIM;
    constexpr int NTOT = (MODE == 1) ? 2 * I_DIM : H_DIM;

    int tile = blockIdx.y;
    if (tile >= g_ntiles) return;
    int e  = g_tile_e[tile];
    int m0 = g_tile_m0[tile];
    int ne = g_counts[e];
    int n0 = blockIdx.x * BN;

    __shared__ float As[BK][BM + 4];
    __shared__ float Bs[BK][BN + 4];

    const float* A = (MODE == 1) ? Ain : (const float*)g_act;
    float* C = (MODE == 1) ? (float*)g_gu : (float*)g_outp;
    const float* B = W + (size_t)e * NTOT * KDIM;

    int tid = threadIdx.x;
    int lm = tid >> 1;             // 0..127
    int lk = (tid & 1) * 8;        // 0 or 8
    int tx = tid & 15, ty = tid >> 4;

    int code0 = g_list[e * T_TOK + min(m0 + lm, ne - 1)];
    int arow = (MODE == 1) ? (code0 >> 1) : code0;
    const float* Ap = A + (size_t)arow * KDIM + lk;
    const float* Bp = B + (size_t)(n0 + lm) * KDIM + lk;

    // prologue: stage first k-tile in registers
    float4 ra0 = *(const float4*)(Ap);
    float4 ra1 = *(const float4*)(Ap + 4);
    float4 rb0 = *(const float4*)(Bp);
    float4 rb1 = *(const float4*)(Bp + 4);

    float acc[8][8] = {};

    for (int k0 = 0; k0 < KDIM; k0 += BK) {
        As[lk+0][lm]=ra0.x; As[lk+1][lm]=ra0.y; As[lk+2][lm]=ra0.z; As[lk+3][lm]=ra0.w;
        As[lk+4][lm]=ra1.x; As[lk+5][lm]=ra1.y; As[lk+6][lm]=ra1.z; As[lk+7][lm]=ra1.w;
        Bs[lk+0][lm]=rb0.x; Bs[lk+1][lm]=rb0.y; Bs[lk+2][lm]=rb0.z; Bs[lk+3][lm]=rb0.w;
        Bs[lk+4][lm]=rb1.x; Bs[lk+5][lm]=rb1.y; Bs[lk+6][lm]=rb1.z; Bs[lk+7][lm]=rb1.w;
        __syncthreads();

        if (k0 + BK < KDIM) {
            ra0 = *(const float4*)(Ap + k0 + BK);
            ra1 = *(const float4*)(Ap + k0 + BK + 4);
            rb0 = *(const float4*)(Bp + k0 + BK);
            rb1 = *(const float4*)(Bp + k0 + BK + 4);
        }

        #pragma unroll
        for (int kk = 0; kk < BK; kk++) {
            float4 a0 = *(const float4*)&As[kk][ty*8];
            float4 a1 = *(const float4*)&As[kk][ty*8 + 4];
            float4 b0 = *(const float4*)&Bs[kk][tx*8];
            float4 b1 = *(const float4*)&Bs[kk][tx*8 + 4];
            float av[8] = {a0.x,a0.y,a0.z,a0.w,a1.x,a1.y,a1.z,a1.w};
            float bv[8] = {b0.x,b0.y,b0.z,b0.w,b1.x,b1.y,b1.z,b1.w};
            #pragma unroll
            for (int i = 0; i < 8; i++)
                #pragma unroll
                for (int j = 0; j < 8; j++)
                    acc[i][j] += av[i] * bv[j];
        }
        __syncthreads();
    }

    #pragma unroll
    for (int i = 0; i < 8; i++) {
        int m = m0 + ty*8 + i;
        if (m < ne) {
            int c = g_list[e * T_TOK + m];
            float* dst = C + (size_t)c * NTOT + n0 + tx*8;
            float4 o0 = make_float4(acc[i][0],acc[i][1],acc[i][2],acc[i][3]);
            float4 o1 = make_float4(acc[i][4],acc[i][5],acc[i][6],acc[i][7]);
            *(float4*)(dst)     = o0;
            *(float4*)(dst + 4) = o1;
        }
    }
}

// ------------------------------------------------------------------
// SwiGLU: act[c, i] = silu(gu[c, i]) * gu[c, I + i]
__global__ void swiglu_kernel()
{
    int c = blockIdx.x;
    const float4* gp = (const float4*)(g_gu + (size_t)c * (2 * I_DIM));
    const float4* up = (const float4*)(g_gu + (size_t)c * (2 * I_DIM) + I_DIM);
    float4* dst = (float4*)(g_act + (size_t)c * I_DIM);
    #pragma unroll
    for (int j = threadIdx.x; j < I_DIM / 4; j += 256) {
        float4 g = gp[j], u = up[j];
        float4 r;
        r.x = (g.x / (1.f + expf(-g.x))) * u.x;
        r.y = (g.y / (1.f + expf(-g.y))) * u.y;
        r.z = (g.z / (1.f + expf(-g.z))) * u.z;
        r.w = (g.w / (1.f + expf(-g.w))) * u.w;
        dst[j] = r;
    }
}

// ------------------------------------------------------------------
// y[t] = w0 * outp[2t] + w1 * outp[2t+1]
__global__ void combine_kernel(float* __restrict__ y)
{
    int t = blockIdx.x;
    float w0 = g_topw[t*2 + 0];
    float w1 = g_topw[t*2 + 1];
    const float4* a = (const float4*)(g_outp + (size_t)(t*2    ) * H_DIM);
    const float4* b = (const float4*)(g_outp + (size_t)(t*2 + 1) * H_DIM);
    float4* o = (float4*)(y + (size_t)t * H_DIM);
    int i = threadIdx.x;
    float4 av = a[i], bv = b[i];
    float4 r;
    r.x = w0*av.x + w1*bv.x;
    r.y = w0*av.y + w1*bv.y;
    r.z = w0*av.z + w1*bv.z;
    r.w = w0*av.w + w1*bv.w;
    o[i] = r;
}

// ------------------------------------------------------------------
extern "C" void kernel_launch(void* const* d_in, const int* in_sizes, int n_in,
                              void* d_out, int out_size)
{
    const float* x    = (const float*)d_in[0];   // [2048, 1024]
    const float* wqkv = (const float*)d_in[1];   // [96, 1024]
    const float* ws   = (const float*)d_in[2];   // [32, 4096, 1024]
    const float* w2s  = (const float*)d_in[3];   // [32, 1024, 2048]
    float* y = (float*)d_out;                    // [2048, 1024]

    zero_counts_kernel<<<1, 32>>>();

    dim3 gmix(2, T_TOK / 64);
    mix_gemm_kernel<<<gmix, 256>>>(x, wqkv);

    route_kernel<<<T_TOK / 4, 128>>>();

    build_tiles_kernel<<<1, 32>>>();

    // GEMM1: gu[code, :4096] = x[code>>1] @ ws_e^T   (K = 1024)
    dim3 g1((2 * I_DIM) / BN, MAX_TILES);        // (32, 64)
    moe_gemm_kernel<1><<<g1, NTHREADS>>>(x, ws);

    swiglu_kernel<<<T_TOK * 2, 256>>>();

    // GEMM2: outp[code, :1024] = act[code] @ w2_e^T  (K = 2048)
    dim3 g2(H_DIM / BN, MAX_TILES);              // (8, 64)
    moe_gemm_kernel<2><<<g2, NTHREADS>>>(nullptr, w2s);

    combine_kernel<<<T_TOK, 256>>>(y);
}

// round 4
// speedup vs baseline: 1.4797x; 1.4797x over previous
#include <cuda_runtime.h>
#include <math.h>

// Problem constants
#define T_TOK 2048
#define H_DIM 1024
#define E_EXP 32
#define I_DIM 2048

// Tile config
#define BM 128
#define BN 128
#define BK 16
#define NTHREADS 256
#define MAX_TILES 64

// -------- scratch (static device globals; no runtime allocation) --------
__device__ float g_mix[T_TOK * 96];
__device__ float g_topw[T_TOK * 2];
__device__ int   g_counts[E_EXP];
__device__ int   g_list[E_EXP * T_TOK];
__device__ int   g_tile_e[MAX_TILES];
__device__ int   g_tile_m0[MAX_TILES];
__device__ int   g_ntiles;
__device__ float g_gu  [(size_t)T_TOK * 2 * 2 * I_DIM]; // gate/up GEMM out (64 MB)
__device__ float g_act [(size_t)T_TOK * 2 * I_DIM];     // SwiGLU act      (32 MB)
__device__ float g_outp[(size_t)T_TOK * 2 * H_DIM];     // per-pair out    (16 MB)

// ------------------------------------------------------------------
__global__ void zero_counts_kernel() {
    if (threadIdx.x < E_EXP) g_counts[threadIdx.x] = 0;
}

// ------------------------------------------------------------------
// mix = x @ wqkv^T   [2048, 96], K=1024
__global__ __launch_bounds__(256) void mix_gemm_kernel(
    const float* __restrict__ x, const float* __restrict__ wqkv)
{
    __shared__ float As[16][64];
    __shared__ float Bs[16][64];
    const int N = 96, K = H_DIM;
    int m0 = blockIdx.y * 64, n0 = blockIdx.x * 64;
    int tid = threadIdx.x;
    int tx = tid & 15, ty = tid >> 4;
    int lm = tid >> 2, lk = (tid & 3) * 4;

    const float* Arow = x + (size_t)(m0 + lm) * K;
    int brow = n0 + lm;
    const float* Brow = wqkv + (size_t)min(brow, N - 1) * K;
    bool bvalid = brow < N;

    float acc[4][4] = {};
    for (int k0 = 0; k0 < K; k0 += 16) {
        float4 av = *(const float4*)(Arow + k0 + lk);
        float4 bv = bvalid ? *(const float4*)(Brow + k0 + lk) : make_float4(0.f,0.f,0.f,0.f);
        As[lk+0][lm]=av.x; As[lk+1][lm]=av.y; As[lk+2][lm]=av.z; As[lk+3][lm]=av.w;
        Bs[lk+0][lm]=bv.x; Bs[lk+1][lm]=bv.y; Bs[lk+2][lm]=bv.z; Bs[lk+3][lm]=bv.w;
        __syncthreads();
        #pragma unroll
        for (int kk = 0; kk < 16; kk++) {
            float4 a = *(const float4*)&As[kk][ty*4];
            float4 b = *(const float4*)&Bs[kk][tx*4];
            float ar[4] = {a.x,a.y,a.z,a.w};
            float br[4] = {b.x,b.y,b.z,b.w};
            #pragma unroll
            for (int i = 0; i < 4; i++)
                #pragma unroll
                for (int j = 0; j < 4; j++)
                    acc[i][j] += ar[i] * br[j];
        }
        __syncthreads();
    }
    #pragma unroll
    for (int i = 0; i < 4; i++) {
        int m = m0 + ty*4 + i;
        #pragma unroll
        for (int j = 0; j < 4; j++) {
            int n = n0 + tx*4 + j;
            if (n < N) g_mix[(size_t)m * 96 + n] = acc[i][j];
        }
    }
}

// ------------------------------------------------------------------
// Router
__global__ void route_kernel()
{
    int t = blockIdx.x * 4 + (threadIdx.x >> 5);
    int lane = threadIdx.x & 31;
    if (t >= T_TOK) return;
    const float* mix = g_mix + (size_t)t * 96;
    float q  = mix[lane];
    float kf = mix[32 + lane];
    float vf = mix[64 + lane];

    float m = -INFINITY;
    #pragma unroll
    for (int f = 0; f < 32; f++) {
        float kk = __shfl_sync(0xffffffffu, kf, f);
        m = fmaxf(m, q * kk);
    }
    float s = 0.f, num = 0.f;
    #pragma unroll
    for (int f = 0; f < 32; f++) {
        float kk = __shfl_sync(0xffffffffu, kf, f);
        float vv = __shfl_sync(0xffffffffu, vf, f);
        float p = expf(q * kk - m);
        s += p; num += p * vv;
    }
    float logit = num / s;

    float v1 = logit; int i1 = lane;
    #pragma unroll
    for (int off = 16; off > 0; off >>= 1) {
        float ov = __shfl_xor_sync(0xffffffffu, v1, off);
        int   oi = __shfl_xor_sync(0xffffffffu, i1, off);
        if (ov > v1 || (ov == v1 && oi < i1)) { v1 = ov; i1 = oi; }
    }
    float mval = (lane == i1) ? -INFINITY : logit;
    float v2 = mval; int i2 = lane;
    #pragma unroll
    for (int off = 16; off > 0; off >>= 1) {
        float ov = __shfl_xor_sync(0xffffffffu, v2, off);
        int   oi = __shfl_xor_sync(0xffffffffu, i2, off);
        if (ov > v2 || (ov == v2 && oi < i2)) { v2 = ov; i2 = oi; }
    }

    if (lane == 0) {
        float e2 = expf(v2 - v1);
        float inv = 1.f / (1.f + e2);
        g_topw[t*2 + 0] = inv;
        g_topw[t*2 + 1] = e2 * inv;
        int p1 = atomicAdd(&g_counts[i1], 1);
        g_list[i1 * T_TOK + p1] = t*2 + 0;
        int p2 = atomicAdd(&g_counts[i2], 1);
        g_list[i2 * T_TOK + p2] = t*2 + 1;
    }
}

// ------------------------------------------------------------------
__global__ void build_tiles_kernel()
{
    int e = threadIdx.x;
    int ne = g_counts[e];
    int ct = (ne + BM - 1) / BM;
    int pre = ct;
    #pragma unroll
    for (int off = 1; off < 32; off <<= 1) {
        int v = __shfl_up_sync(0xffffffffu, pre, off);
        if (e >= off) pre += v;
    }
    int start = pre - ct;
    for (int i = 0; i < ct; i++) {
        g_tile_e[start + i]  = e;
        g_tile_m0[start + i] = i * BM;
    }
    if (e == 31) g_ntiles = pre;
}

// ------------------------------------------------------------------
// Gathered GEMM, 128x128x16 tile, 8x8 microtile split as 2x2 of 4x4
// (conflict-free LDS/STS).
// MODE 1: g_gu[code,:] = x[code>>1,:] @ ws_e^T   (K=1024, N=4096)
// MODE 2: g_outp[code,:] = g_act[code,:] @ w2_e^T (K=2048, N=1024)
template<int MODE>
__global__ __launch_bounds__(NTHREADS, 2) void moe_gemm_kernel(
    const float* __restrict__ Ain, const float* __restrict__ W)
{
    constexpr int KDIM = (MODE == 1) ? H_DIM : I_DIM;
    constexpr int NTOT = (MODE == 1) ? 2 * I_DIM : H_DIM;

    int tile = blockIdx.y;
    if (tile >= g_ntiles) return;
    int e  = g_tile_e[tile];
    int m0 = g_tile_m0[tile];
    int ne = g_counts[e];
    int n0 = blockIdx.x * BN;

    __shared__ float As[BK][BM + 4];
    __shared__ float Bs[BK][BN + 4];

    const float* A = (MODE == 1) ? Ain : (const float*)g_act;
    float* C = (MODE == 1) ? (float*)g_gu : (float*)g_outp;
    const float* B = W + (size_t)e * NTOT * KDIM;

    int tid = threadIdx.x;
    // loader mapping: warp-uniform lk, 32 consecutive lm per warp (STS conflict-free)
    int lm = tid & 127;
    int lk = (tid >> 7) * 8;
    // compute mapping
    int tx = tid & 15, ty = tid >> 4;

    int code0 = g_list[e * T_TOK + min(m0 + lm, ne - 1)];
    int arow = (MODE == 1) ? (code0 >> 1) : code0;
    const float* Ap = A + (size_t)arow * KDIM + lk;
    const float* Bp = B + (size_t)(n0 + lm) * KDIM + lk;

    float acc[8][8] = {};

    for (int k0 = 0; k0 < KDIM; k0 += BK) {
        float4 a0 = *(const float4*)(Ap + k0);
        float4 a1 = *(const float4*)(Ap + k0 + 4);
        float4 b0 = *(const float4*)(Bp + k0);
        float4 b1 = *(const float4*)(Bp + k0 + 4);
        As[lk+0][lm]=a0.x; As[lk+1][lm]=a0.y; As[lk+2][lm]=a0.z; As[lk+3][lm]=a0.w;
        As[lk+4][lm]=a1.x; As[lk+5][lm]=a1.y; As[lk+6][lm]=a1.z; As[lk+7][lm]=a1.w;
        Bs[lk+0][lm]=b0.x; Bs[lk+1][lm]=b0.y; Bs[lk+2][lm]=b0.z; Bs[lk+3][lm]=b0.w;
        Bs[lk+4][lm]=b1.x; Bs[lk+5][lm]=b1.y; Bs[lk+6][lm]=b1.z; Bs[lk+7][lm]=b1.w;
        __syncthreads();

        #pragma unroll
        for (int kk = 0; kk < BK; kk++) {
            float4 fa0 = *(const float4*)&As[kk][ty*4];
            float4 fa1 = *(const float4*)&As[kk][64 + ty*4];
            float4 fb0 = *(const float4*)&Bs[kk][tx*4];
            float4 fb1 = *(const float4*)&Bs[kk][64 + tx*4];
            float av[8] = {fa0.x,fa0.y,fa0.z,fa0.w, fa1.x,fa1.y,fa1.z,fa1.w};
            float bv[8] = {fb0.x,fb0.y,fb0.z,fb0.w, fb1.x,fb1.y,fb1.z,fb1.w};
            #pragma unroll
            for (int i = 0; i < 8; i++)
                #pragma unroll
                for (int j = 0; j < 8; j++)
                    acc[i][j] += av[i] * bv[j];
        }
        __syncthreads();
    }

    // epilogue: rows {ty*4+i, 64+ty*4+i}, cols {tx*4+j, 64+tx*4+j}
    #pragma unroll
    for (int ih = 0; ih < 2; ih++) {
        #pragma unroll
        for (int i = 0; i < 4; i++) {
            int m = m0 + ih*64 + ty*4 + i;
            if (m < ne) {
                int c = g_list[e * T_TOK + m];
                float* dst = C + (size_t)c * NTOT + n0;
                int r = ih*4 + i;
                *(float4*)(dst + tx*4)      = make_float4(acc[r][0],acc[r][1],acc[r][2],acc[r][3]);
                *(float4*)(dst + 64 + tx*4) = make_float4(acc[r][4],acc[r][5],acc[r][6],acc[r][7]);
            }
        }
    }
}

// ------------------------------------------------------------------
__global__ void swiglu_kernel()
{
    int c = blockIdx.x;
    const float4* gp = (const float4*)(g_gu + (size_t)c * (2 * I_DIM));
    const float4* up = (const float4*)(g_gu + (size_t)c * (2 * I_DIM) + I_DIM);
    float4* dst = (float4*)(g_act + (size_t)c * I_DIM);
    #pragma unroll
    for (int j = threadIdx.x; j < I_DIM / 4; j += 256) {
        float4 g = gp[j], u = up[j];
        float4 r;
        r.x = (g.x / (1.f + expf(-g.x))) * u.x;
        r.y = (g.y / (1.f + expf(-g.y))) * u.y;
        r.z = (g.z / (1.f + expf(-g.z))) * u.z;
        r.w = (g.w / (1.f + expf(-g.w))) * u.w;
        dst[j] = r;
    }
}

// ------------------------------------------------------------------
__global__ void combine_kernel(float* __restrict__ y)
{
    int t = blockIdx.x;
    float w0 = g_topw[t*2 + 0];
    float w1 = g_topw[t*2 + 1];
    const float4* a = (const float4*)(g_outp + (size_t)(t*2    ) * H_DIM);
    const float4* b = (const float4*)(g_outp + (size_t)(t*2 + 1) * H_DIM);
    float4* o = (float4*)(y + (size_t)t * H_DIM);
    int i = threadIdx.x;
    float4 av = a[i], bv = b[i];
    float4 r;
    r.x = w0*av.x + w1*bv.x;
    r.y = w0*av.y + w1*bv.y;
    r.z = w0*av.z + w1*bv.z;
    r.w = w0*av.w + w1*bv.w;
    o[i] = r;
}

// ------------------------------------------------------------------
extern "C" void kernel_launch(void* const* d_in, const int* in_sizes, int n_in,
                              void* d_out, int out_size)
{
    const float* x    = (const float*)d_in[0];   // [2048, 1024]
    const float* wqkv = (const float*)d_in[1];   // [96, 1024]
    const float* ws   = (const float*)d_in[2];   // [32, 4096, 1024]
    const float* w2s  = (const float*)d_in[3];   // [32, 1024, 2048]
    float* y = (float*)d_out;                    // [2048, 1024]

    zero_counts_kernel<<<1, 32>>>();

    dim3 gmix(2, T_TOK / 64);
    mix_gemm_kernel<<<gmix, 256>>>(x, wqkv);

    route_kernel<<<T_TOK / 4, 128>>>();

    build_tiles_kernel<<<1, 32>>>();

    dim3 g1((2 * I_DIM) / BN, MAX_TILES);        // (32, 64)
    moe_gemm_kernel<1><<<g1, NTHREADS>>>(x, ws);

    swiglu_kernel<<<T_TOK * 2, 256>>>();

    dim3 g2(H_DIM / BN, MAX_TILES);              // (8, 64)
    moe_gemm_kernel<2><<<g2, NTHREADS>>>(nullptr, w2s);

    combine_kernel<<<T_TOK, 256>>>(y);
}

// round 5
// speedup vs baseline: 2.6262x; 1.7748x over previous
#include <cuda_runtime.h>
#include <math.h>
#include <stdint.h>

// Problem constants
#define T_TOK 2048
#define H_DIM 1024
#define E_EXP 32
#define I_DIM 2048

// Tile config
#define BM 128
#define BN 128
#define NTHREADS 256
#define MAX_TILES 64
#define SSTRIDE 36   // 32 + 4 pad (words)

// -------- scratch (static device globals) --------
__device__ float g_mix[T_TOK * 96];
__device__ float g_topw[T_TOK * 2];
__device__ int   g_counts[E_EXP];
__device__ int   g_list[E_EXP * T_TOK];
__device__ int   g_tile_e[MAX_TILES];
__device__ int   g_tile_m0[MAX_TILES];
__device__ int   g_ntiles;
__device__ float g_gu  [(size_t)T_TOK * 2 * 2 * I_DIM]; // gate/up GEMM out (64 MB)
__device__ float g_act [(size_t)T_TOK * 2 * I_DIM];     // SwiGLU act      (32 MB)
__device__ float g_outp[(size_t)T_TOK * 2 * H_DIM];     // per-pair out    (16 MB)

// ------------------------------------------------------------------
__global__ void zero_counts_kernel() {
    if (threadIdx.x < E_EXP) g_counts[threadIdx.x] = 0;
}

// ------------------------------------------------------------------
// mix = x @ wqkv^T   [2048, 96], K=1024  (fp32, small)
__global__ __launch_bounds__(256) void mix_gemm_kernel(
    const float* __restrict__ x, const float* __restrict__ wqkv)
{
    __shared__ float As[16][64];
    __shared__ float Bs[16][64];
    const int N = 96, K = H_DIM;
    int m0 = blockIdx.y * 64, n0 = blockIdx.x * 64;
    int tid = threadIdx.x;
    int tx = tid & 15, ty = tid >> 4;
    int lm = tid >> 2, lk = (tid & 3) * 4;

    const float* Arow = x + (size_t)(m0 + lm) * K;
    int brow = n0 + lm;
    const float* Brow = wqkv + (size_t)min(brow, N - 1) * K;
    bool bvalid = brow < N;

    float acc[4][4] = {};
    for (int k0 = 0; k0 < K; k0 += 16) {
        float4 av = *(const float4*)(Arow + k0 + lk);
        float4 bv = bvalid ? *(const float4*)(Brow + k0 + lk) : make_float4(0.f,0.f,0.f,0.f);
        As[lk+0][lm]=av.x; As[lk+1][lm]=av.y; As[lk+2][lm]=av.z; As[lk+3][lm]=av.w;
        Bs[lk+0][lm]=bv.x; Bs[lk+1][lm]=bv.y; Bs[lk+2][lm]=bv.z; Bs[lk+3][lm]=bv.w;
        __syncthreads();
        #pragma unroll
        for (int kk = 0; kk < 16; kk++) {
            float4 a = *(const float4*)&As[kk][ty*4];
            float4 b = *(const float4*)&Bs[kk][tx*4];
            float ar[4] = {a.x,a.y,a.z,a.w};
            float br[4] = {b.x,b.y,b.z,b.w};
            #pragma unroll
            for (int i = 0; i < 4; i++)
                #pragma unroll
                for (int j = 0; j < 4; j++)
                    acc[i][j] += ar[i] * br[j];
        }
        __syncthreads();
    }
    #pragma unroll
    for (int i = 0; i < 4; i++) {
        int m = m0 + ty*4 + i;
        #pragma unroll
        for (int j = 0; j < 4; j++) {
            int n = n0 + tx*4 + j;
            if (n < N) g_mix[(size_t)m * 96 + n] = acc[i][j];
        }
    }
}

// ------------------------------------------------------------------
__global__ void route_kernel()
{
    int t = blockIdx.x * 4 + (threadIdx.x >> 5);
    int lane = threadIdx.x & 31;
    if (t >= T_TOK) return;
    const float* mix = g_mix + (size_t)t * 96;
    float q  = mix[lane];
    float kf = mix[32 + lane];
    float vf = mix[64 + lane];

    float m = -INFINITY;
    #pragma unroll
    for (int f = 0; f < 32; f++) {
        float kk = __shfl_sync(0xffffffffu, kf, f);
        m = fmaxf(m, q * kk);
    }
    float s = 0.f, num = 0.f;
    #pragma unroll
    for (int f = 0; f < 32; f++) {
        float kk = __shfl_sync(0xffffffffu, kf, f);
        float vv = __shfl_sync(0xffffffffu, vf, f);
        float p = expf(q * kk - m);
        s += p; num += p * vv;
    }
    float logit = num / s;

    float v1 = logit; int i1 = lane;
    #pragma unroll
    for (int off = 16; off > 0; off >>= 1) {
        float ov = __shfl_xor_sync(0xffffffffu, v1, off);
        int   oi = __shfl_xor_sync(0xffffffffu, i1, off);
        if (ov > v1 || (ov == v1 && oi < i1)) { v1 = ov; i1 = oi; }
    }
    float mval = (lane == i1) ? -INFINITY : logit;
    float v2 = mval; int i2 = lane;
    #pragma unroll
    for (int off = 16; off > 0; off >>= 1) {
        float ov = __shfl_xor_sync(0xffffffffu, v2, off);
        int   oi = __shfl_xor_sync(0xffffffffu, i2, off);
        if (ov > v2 || (ov == v2 && oi < i2)) { v2 = ov; i2 = oi; }
    }

    if (lane == 0) {
        float e2 = expf(v2 - v1);
        float inv = 1.f / (1.f + e2);
        g_topw[t*2 + 0] = inv;
        g_topw[t*2 + 1] = e2 * inv;
        int p1 = atomicAdd(&g_counts[i1], 1);
        g_list[i1 * T_TOK + p1] = t*2 + 0;
        int p2 = atomicAdd(&g_counts[i2], 1);
        g_list[i2 * T_TOK + p2] = t*2 + 1;
    }
}

// ------------------------------------------------------------------
__global__ void build_tiles_kernel()
{
    int e = threadIdx.x;
    int ne = g_counts[e];
    int ct = (ne + BM - 1) / BM;
    int pre = ct;
    #pragma unroll
    for (int off = 1; off < 32; off <<= 1) {
        int v = __shfl_up_sync(0xffffffffu, pre, off);
        if (e >= off) pre += v;
    }
    int start = pre - ct;
    for (int i = 0; i < ct; i++) {
        g_tile_e[start + i]  = e;
        g_tile_m0[start + i] = i * BM;
    }
    if (e == 31) g_ntiles = pre;
}

// ------------------------------------------------------------------
__device__ __forceinline__ uint32_t f2tf32(float f) {
    uint32_t u;
    asm("cvt.rna.tf32.f32 %0, %1;" : "=r"(u) : "f"(f));
    return u;
}

// Gathered GEMM on tensor cores (tf32 m16n8k8).
// MODE 1: g_gu[code,:]   = x[code>>1,:] @ ws_e^T   (K=1024, N=4096)
// MODE 2: g_outp[code,:] = g_act[code,:] @ w2_e^T  (K=2048, N=1024)
template<int MODE>
__global__ __launch_bounds__(NTHREADS, 2) void moe_gemm_tc_kernel(
    const float* __restrict__ Ain, const float* __restrict__ W)
{
    constexpr int KDIM = (MODE == 1) ? H_DIM : I_DIM;
    constexpr int NTOT = (MODE == 1) ? 2 * I_DIM : H_DIM;

    int tile = blockIdx.y;
    if (tile >= g_ntiles) return;
    int e  = g_tile_e[tile];
    int m0 = g_tile_m0[tile];
    int ne = g_counts[e];
    int n0 = blockIdx.x * BN;

    __shared__ float As[BM][SSTRIDE];   // [m][k], k-tile of 32
    __shared__ float Bs[BN][SSTRIDE];   // [n][k]

    const float* A = (MODE == 1) ? Ain : (const float*)g_act;
    float* C = (MODE == 1) ? (float*)g_gu : (float*)g_outp;
    const float* B = W + (size_t)e * NTOT * KDIM;

    int tid = threadIdx.x;
    int lr = tid & 127;              // loader row
    int lc = (tid >> 7) * 16;        // loader col base (0 / 16)

    int code0 = g_list[e * T_TOK + min(m0 + lr, ne - 1)];
    int arow = (MODE == 1) ? (code0 >> 1) : code0;
    const float* Ap = A + (size_t)arow * KDIM + lc;
    const float* Bp = B + (size_t)(n0 + lr) * KDIM + lc;

    int wid = tid >> 5, lane = tid & 31;
    int wm = wid >> 2, wn = wid & 3;       // 2 x 4 warp grid
    int qr = lane >> 2, qc = lane & 3;     // quad row / col

    float acc[4][4][4] = {};               // [mt][nt][reg]

    for (int k0 = 0; k0 < KDIM; k0 += 32) {
        #pragma unroll
        for (int j = 0; j < 4; j++) {
            float4 av = *(const float4*)(Ap + k0 + j*4);
            float4 bv = *(const float4*)(Bp + k0 + j*4);
            *(float4*)&As[lr][lc + j*4] = av;
            *(float4*)&Bs[lr][lc + j*4] = bv;
        }
        __syncthreads();

        #pragma unroll
        for (int kk = 0; kk < 32; kk += 8) {
            uint32_t afr[4][4];
            #pragma unroll
            for (int mt = 0; mt < 4; mt++) {
                int mr = wm*64 + mt*16 + qr;
                afr[mt][0] = f2tf32(As[mr    ][kk     + qc]);
                afr[mt][1] = f2tf32(As[mr + 8][kk     + qc]);
                afr[mt][2] = f2tf32(As[mr    ][kk + 4 + qc]);
                afr[mt][3] = f2tf32(As[mr + 8][kk + 4 + qc]);
            }
            uint32_t bfr[4][2];
            #pragma unroll
            for (int nt = 0; nt < 4; nt++) {
                int nr = wn*32 + nt*8 + qr;
                bfr[nt][0] = f2tf32(Bs[nr][kk     + qc]);
                bfr[nt][1] = f2tf32(Bs[nr][kk + 4 + qc]);
            }
            #pragma unroll
            for (int mt = 0; mt < 4; mt++)
                #pragma unroll
                for (int nt = 0; nt < 4; nt++) {
                    asm volatile(
                        "mma.sync.aligned.m16n8k8.row.col.f32.tf32.tf32.f32 "
                        "{%0,%1,%2,%3}, {%4,%5,%6,%7}, {%8,%9}, {%0,%1,%2,%3};"
                        : "+f"(acc[mt][nt][0]), "+f"(acc[mt][nt][1]),
                          "+f"(acc[mt][nt][2]), "+f"(acc[mt][nt][3])
                        : "r"(afr[mt][0]), "r"(afr[mt][1]),
                          "r"(afr[mt][2]), "r"(afr[mt][3]),
                          "r"(bfr[nt][0]), "r"(bfr[nt][1]));
                }
        }
        __syncthreads();
    }

    // epilogue: acc reg r: c0:(qr, 2qc) c1:(qr, 2qc+1) c2:(qr+8, 2qc) c3:(qr+8, 2qc+1)
    #pragma unroll
    for (int mt = 0; mt < 4; mt++) {
        int r0 = m0 + wm*64 + mt*16 + qr;
        int r1 = r0 + 8;
        bool v0 = r0 < ne, v1 = r1 < ne;
        int c0 = v0 ? g_list[e * T_TOK + r0] : 0;
        int c1 = v1 ? g_list[e * T_TOK + r1] : 0;
        float* d0 = C + (size_t)c0 * NTOT + n0 + wn*32;
        float* d1 = C + (size_t)c1 * NTOT + n0 + wn*32;
        #pragma unroll
        for (int nt = 0; nt < 4; nt++) {
            int col = nt*8 + 2*qc;
            if (v0) *(float2*)(d0 + col) = make_float2(acc[mt][nt][0], acc[mt][nt][1]);
            if (v1) *(float2*)(d1 + col) = make_float2(acc[mt][nt][2], acc[mt][nt][3]);
        }
    }
}

// ------------------------------------------------------------------
__global__ void swiglu_kernel()
{
    int c = blockIdx.x;
    const float4* gp = (const float4*)(g_gu + (size_t)c * (2 * I_DIM));
    const float4* up = (const float4*)(g_gu + (size_t)c * (2 * I_DIM) + I_DIM);
    float4* dst = (float4*)(g_act + (size_t)c * I_DIM);
    #pragma unroll
    for (int j = threadIdx.x; j < I_DIM / 4; j += 256) {
        float4 g = gp[j], u = up[j];
        float4 r;
        r.x = (g.x / (1.f + expf(-g.x))) * u.x;
        r.y = (g.y / (1.f + expf(-g.y))) * u.y;
        r.z = (g.z / (1.f + expf(-g.z))) * u.z;
        r.w = (g.w / (1.f + expf(-g.w))) * u.w;
        dst[j] = r;
    }
}

// ------------------------------------------------------------------
__global__ void combine_kernel(float* __restrict__ y)
{
    int t = blockIdx.x;
    float w0 = g_topw[t*2 + 0];
    float w1 = g_topw[t*2 + 1];
    const float4* a = (const float4*)(g_outp + (size_t)(t*2    ) * H_DIM);
    const float4* b = (const float4*)(g_outp + (size_t)(t*2 + 1) * H_DIM);
    float4* o = (float4*)(y + (size_t)t * H_DIM);
    int i = threadIdx.x;
    float4 av = a[i], bv = b[i];
    float4 r;
    r.x = w0*av.x + w1*bv.x;
    r.y = w0*av.y + w1*bv.y;
    r.z = w0*av.z + w1*bv.z;
    r.w = w0*av.w + w1*bv.w;
    o[i] = r;
}

// ------------------------------------------------------------------
extern "C" void kernel_launch(void* const* d_in, const int* in_sizes, int n_in,
                              void* d_out, int out_size)
{
    const float* x    = (const float*)d_in[0];   // [2048, 1024]
    const float* wqkv = (const float*)d_in[1];   // [96, 1024]
    const float* ws   = (const float*)d_in[2];   // [32, 4096, 1024]
    const float* w2s  = (const float*)d_in[3];   // [32, 1024, 2048]
    float* y = (float*)d_out;                    // [2048, 1024]

    zero_counts_kernel<<<1, 32>>>();

    dim3 gmix(2, T_TOK / 64);
    mix_gemm_kernel<<<gmix, 256>>>(x, wqkv);

    route_kernel<<<T_TOK / 4, 128>>>();

    build_tiles_kernel<<<1, 32>>>();

    dim3 g1((2 * I_DIM) / BN, MAX_TILES);        // (32, 64)
    moe_gemm_tc_kernel<1><<<g1, NTHREADS>>>(x, ws);

    swiglu_kernel<<<T_TOK * 2, 256>>>();

    dim3 g2(H_DIM / BN, MAX_TILES);              // (8, 64)
    moe_gemm_tc_kernel<2><<<g2, NTHREADS>>>(nullptr, w2s);

    combine_kernel<<<T_TOK, 256>>>(y);
}

// round 6
// speedup vs baseline: 2.8707x; 1.0931x over previous
#include <cuda_runtime.h>
#include <math.h>
#include <stdint.h>

// Problem constants
#define T_TOK 2048
#define H_DIM 1024
#define E_EXP 32
#define I_DIM 2048

// Tile config
#define BM 128
#define BN 128
#define BK 16
#define NTHREADS 256
#define MAX_TILES 64
#define SROW 20   // 16 + 4 pad (words)

// -------- scratch (static device globals) --------
__device__ float g_mix[T_TOK * 96];
__device__ float g_topw[T_TOK * 2];
__device__ int   g_counts[E_EXP];
__device__ int   g_list[E_EXP * T_TOK];
__device__ int   g_tile_e[MAX_TILES];
__device__ int   g_tile_m0[MAX_TILES];
__device__ int   g_ntiles;
__device__ float g_gu  [(size_t)T_TOK * 2 * 2 * I_DIM]; // gate/up GEMM out (64 MB)
__device__ float g_act [(size_t)T_TOK * 2 * I_DIM];     // SwiGLU act      (32 MB)
__device__ float g_outp[(size_t)T_TOK * 2 * H_DIM];     // per-pair out    (16 MB)

// ------------------------------------------------------------------
__global__ void zero_counts_kernel() {
    if (threadIdx.x < E_EXP) g_counts[threadIdx.x] = 0;
}

// ------------------------------------------------------------------
// mix = x @ wqkv^T   [2048, 96], K=1024  (fp32, small)
__global__ __launch_bounds__(256) void mix_gemm_kernel(
    const float* __restrict__ x, const float* __restrict__ wqkv)
{
    __shared__ float As[16][64];
    __shared__ float Bs[16][64];
    const int N = 96, K = H_DIM;
    int m0 = blockIdx.y * 64, n0 = blockIdx.x * 64;
    int tid = threadIdx.x;
    int tx = tid & 15, ty = tid >> 4;
    int lm = tid >> 2, lk = (tid & 3) * 4;

    const float* Arow = x + (size_t)(m0 + lm) * K;
    int brow = n0 + lm;
    const float* Brow = wqkv + (size_t)min(brow, N - 1) * K;
    bool bvalid = brow < N;

    float acc[4][4] = {};
    for (int k0 = 0; k0 < K; k0 += 16) {
        float4 av = *(const float4*)(Arow + k0 + lk);
        float4 bv = bvalid ? *(const float4*)(Brow + k0 + lk) : make_float4(0.f,0.f,0.f,0.f);
        As[lk+0][lm]=av.x; As[lk+1][lm]=av.y; As[lk+2][lm]=av.z; As[lk+3][lm]=av.w;
        Bs[lk+0][lm]=bv.x; Bs[lk+1][lm]=bv.y; Bs[lk+2][lm]=bv.z; Bs[lk+3][lm]=bv.w;
        __syncthreads();
        #pragma unroll
        for (int kk = 0; kk < 16; kk++) {
            float4 a = *(const float4*)&As[kk][ty*4];
            float4 b = *(const float4*)&Bs[kk][tx*4];
            float ar[4] = {a.x,a.y,a.z,a.w};
            float br[4] = {b.x,b.y,b.z,b.w};
            #pragma unroll
            for (int i = 0; i < 4; i++)
                #pragma unroll
                for (int j = 0; j < 4; j++)
                    acc[i][j] += ar[i] * br[j];
        }
        __syncthreads();
    }
    #pragma unroll
    for (int i = 0; i < 4; i++) {
        int m = m0 + ty*4 + i;
        #pragma unroll
        for (int j = 0; j < 4; j++) {
            int n = n0 + tx*4 + j;
            if (n < N) g_mix[(size_t)m * 96 + n] = acc[i][j];
        }
    }
}

// ------------------------------------------------------------------
__global__ void route_kernel()
{
    int t = blockIdx.x * 4 + (threadIdx.x >> 5);
    int lane = threadIdx.x & 31;
    if (t >= T_TOK) return;
    const float* mix = g_mix + (size_t)t * 96;
    float q  = mix[lane];
    float kf = mix[32 + lane];
    float vf = mix[64 + lane];

    float m = -INFINITY;
    #pragma unroll
    for (int f = 0; f < 32; f++) {
        float kk = __shfl_sync(0xffffffffu, kf, f);
        m = fmaxf(m, q * kk);
    }
    float s = 0.f, num = 0.f;
    #pragma unroll
    for (int f = 0; f < 32; f++) {
        float kk = __shfl_sync(0xffffffffu, kf, f);
        float vv = __shfl_sync(0xffffffffu, vf, f);
        float p = expf(q * kk - m);
        s += p; num += p * vv;
    }
    float logit = num / s;

    float v1 = logit; int i1 = lane;
    #pragma unroll
    for (int off = 16; off > 0; off >>= 1) {
        float ov = __shfl_xor_sync(0xffffffffu, v1, off);
        int   oi = __shfl_xor_sync(0xffffffffu, i1, off);
        if (ov > v1 || (ov == v1 && oi < i1)) { v1 = ov; i1 = oi; }
    }
    float mval = (lane == i1) ? -INFINITY : logit;
    float v2 = mval; int i2 = lane;
    #pragma unroll
    for (int off = 16; off > 0; off >>= 1) {
        float ov = __shfl_xor_sync(0xffffffffu, v2, off);
        int   oi = __shfl_xor_sync(0xffffffffu, i2, off);
        if (ov > v2 || (ov == v2 && oi < i2)) { v2 = ov; i2 = oi; }
    }

    if (lane == 0) {
        float e2 = expf(v2 - v1);
        float inv = 1.f / (1.f + e2);
        g_topw[t*2 + 0] = inv;
        g_topw[t*2 + 1] = e2 * inv;
        int p1 = atomicAdd(&g_counts[i1], 1);
        g_list[i1 * T_TOK + p1] = t*2 + 0;
        int p2 = atomicAdd(&g_counts[i2], 1);
        g_list[i2 * T_TOK + p2] = t*2 + 1;
    }
}

// ------------------------------------------------------------------
__global__ void build_tiles_kernel()
{
    int e = threadIdx.x;
    int ne = g_counts[e];
    int ct = (ne + BM - 1) / BM;
    int pre = ct;
    #pragma unroll
    for (int off = 1; off < 32; off <<= 1) {
        int v = __shfl_up_sync(0xffffffffu, pre, off);
        if (e >= off) pre += v;
    }
    int start = pre - ct;
    for (int i = 0; i < ct; i++) {
        g_tile_e[start + i]  = e;
        g_tile_m0[start + i] = i * BM;
    }
    if (e == 31) g_ntiles = pre;
}

// ------------------------------------------------------------------
__device__ __forceinline__ uint32_t f2tf32(float f) {
    uint32_t u;
    asm("cvt.rna.tf32.f32 %0, %1;" : "=r"(u) : "f"(f));
    return u;
}

// Gathered GEMM on tensor cores (tf32 m16n8k8).
// smem holds PRE-CONVERTED tf32 bits; double-buffered, 1 sync/iter.
// MODE 1: g_gu[code,:]   = x[code>>1,:] @ ws_e^T   (K=1024, N=4096)
// MODE 2: g_outp[code,:] = g_act[code,:] @ w2_e^T  (K=2048, N=1024)
template<int MODE>
__global__ __launch_bounds__(NTHREADS, 2) void moe_gemm_tc_kernel(
    const float* __restrict__ Ain, const float* __restrict__ W)
{
    constexpr int KDIM = (MODE == 1) ? H_DIM : I_DIM;
    constexpr int NTOT = (MODE == 1) ? 2 * I_DIM : H_DIM;

    int tile = blockIdx.y;
    if (tile >= g_ntiles) return;
    int e  = g_tile_e[tile];
    int m0 = g_tile_m0[tile];
    int ne = g_counts[e];
    int n0 = blockIdx.x * BN;

    __shared__ uint32_t As[2][BM][SROW];
    __shared__ uint32_t Bs[2][BN][SROW];

    const float* A = (MODE == 1) ? Ain : (const float*)g_act;
    float* C = (MODE == 1) ? (float*)g_gu : (float*)g_outp;
    const float* B = W + (size_t)e * NTOT * KDIM;

    int tid = threadIdx.x;
    int lr  = tid & 127;             // loader row
    int lc8 = (tid >> 7) * 8;        // loader col base (0 / 8)

    int code0 = g_list[e * T_TOK + min(m0 + lr, ne - 1)];
    int arow = (MODE == 1) ? (code0 >> 1) : code0;
    const float* Ap = A + (size_t)arow * KDIM + lc8;
    const float* Bp = B + (size_t)(n0 + lr) * KDIM + lc8;

    int wid = tid >> 5, lane = tid & 31;
    int wm = wid >> 2, wn = wid & 3;       // 2 x 4 warp grid (64x32 per warp)
    int qr = lane >> 2, qc = lane & 3;

    float acc[4][4][4] = {};               // [mt][nt][reg]

    // prologue: fetch k-tile 0 into regs
    float4 ra0 = *(const float4*)(Ap);
    float4 ra1 = *(const float4*)(Ap + 4);
    float4 rb0 = *(const float4*)(Bp);
    float4 rb1 = *(const float4*)(Bp + 4);

    int p = 0;
    for (int k0 = 0; k0 < KDIM; k0 += BK) {
        // store current tile (pre-converted) into buffer p
        *(uint4*)&As[p][lr][lc8]     = make_uint4(f2tf32(ra0.x), f2tf32(ra0.y), f2tf32(ra0.z), f2tf32(ra0.w));
        *(uint4*)&As[p][lr][lc8 + 4] = make_uint4(f2tf32(ra1.x), f2tf32(ra1.y), f2tf32(ra1.z), f2tf32(ra1.w));
        *(uint4*)&Bs[p][lr][lc8]     = make_uint4(f2tf32(rb0.x), f2tf32(rb0.y), f2tf32(rb0.z), f2tf32(rb0.w));
        *(uint4*)&Bs[p][lr][lc8 + 4] = make_uint4(f2tf32(rb1.x), f2tf32(rb1.y), f2tf32(rb1.z), f2tf32(rb1.w));
        __syncthreads();

        bool more = (k0 + BK) < KDIM;
        if (more) {
            ra0 = *(const float4*)(Ap + k0 + BK);
            ra1 = *(const float4*)(Ap + k0 + BK + 4);
            rb0 = *(const float4*)(Bp + k0 + BK);
            rb1 = *(const float4*)(Bp + k0 + BK + 4);
        }

        #pragma unroll
        for (int kk = 0; kk < BK; kk += 8) {
            uint32_t afr[4][4];
            #pragma unroll
            for (int mt = 0; mt < 4; mt++) {
                int mr = wm*64 + mt*16 + qr;
                afr[mt][0] = As[p][mr    ][kk     + qc];
                afr[mt][1] = As[p][mr + 8][kk     + qc];
                afr[mt][2] = As[p][mr    ][kk + 4 + qc];
                afr[mt][3] = As[p][mr + 8][kk + 4 + qc];
            }
            uint32_t bfr[4][2];
            #pragma unroll
            for (int nt = 0; nt < 4; nt++) {
                int nr = wn*32 + nt*8 + qr;
                bfr[nt][0] = Bs[p][nr][kk     + qc];
                bfr[nt][1] = Bs[p][nr][kk + 4 + qc];
            }
            #pragma unroll
            for (int mt = 0; mt < 4; mt++)
                #pragma unroll
                for (int nt = 0; nt < 4; nt++) {
                    asm volatile(
                        "mma.sync.aligned.m16n8k8.row.col.f32.tf32.tf32.f32 "
                        "{%0,%1,%2,%3}, {%4,%5,%6,%7}, {%8,%9}, {%0,%1,%2,%3};"
                        : "+f"(acc[mt][nt][0]), "+f"(acc[mt][nt][1]),
                          "+f"(acc[mt][nt][2]), "+f"(acc[mt][nt][3])
                        : "r"(afr[mt][0]), "r"(afr[mt][1]),
                          "r"(afr[mt][2]), "r"(afr[mt][3]),
                          "r"(bfr[nt][0]), "r"(bfr[nt][1]));
                }
        }
        p ^= 1;
    }

    // epilogue
    #pragma unroll
    for (int mt = 0; mt < 4; mt++) {
        int r0 = m0 + wm*64 + mt*16 + qr;
        int r1 = r0 + 8;
        bool v0 = r0 < ne, v1 = r1 < ne;
        int c0 = v0 ? g_list[e * T_TOK + r0] : 0;
        int c1 = v1 ? g_list[e * T_TOK + r1] : 0;
        float* d0 = C + (size_t)c0 * NTOT + n0 + wn*32;
        float* d1 = C + (size_t)c1 * NTOT + n0 + wn*32;
        #pragma unroll
        for (int nt = 0; nt < 4; nt++) {
            int col = nt*8 + 2*qc;
            if (v0) *(float2*)(d0 + col) = make_float2(acc[mt][nt][0], acc[mt][nt][1]);
            if (v1) *(float2*)(d1 + col) = make_float2(acc[mt][nt][2], acc[mt][nt][3]);
        }
    }
}

// ------------------------------------------------------------------
__global__ void swiglu_kernel()
{
    int c = blockIdx.x;
    const float4* gp = (const float4*)(g_gu + (size_t)c * (2 * I_DIM));
    const float4* up = (const float4*)(g_gu + (size_t)c * (2 * I_DIM) + I_DIM);
    float4* dst = (float4*)(g_act + (size_t)c * I_DIM);
    #pragma unroll
    for (int j = threadIdx.x; j < I_DIM / 4; j += 256) {
        float4 g = gp[j], u = up[j];
        float4 r;
        r.x = (g.x / (1.f + expf(-g.x))) * u.x;
        r.y = (g.y / (1.f + expf(-g.y))) * u.y;
        r.z = (g.z / (1.f + expf(-g.z))) * u.z;
        r.w = (g.w / (1.f + expf(-g.w))) * u.w;
        dst[j] = r;
    }
}

// ------------------------------------------------------------------
__global__ void combine_kernel(float* __restrict__ y)
{
    int t = blockIdx.x;
    float w0 = g_topw[t*2 + 0];
    float w1 = g_topw[t*2 + 1];
    const float4* a = (const float4*)(g_outp + (size_t)(t*2    ) * H_DIM);
    const float4* b = (const float4*)(g_outp + (size_t)(t*2 + 1) * H_DIM);
    float4* o = (float4*)(y + (size_t)t * H_DIM);
    int i = threadIdx.x;
    float4 av = a[i], bv = b[i];
    float4 r;
    r.x = w0*av.x + w1*bv.x;
    r.y = w0*av.y + w1*bv.y;
    r.z = w0*av.z + w1*bv.z;
    r.w = w0*av.w + w1*bv.w;
    o[i] = r;
}

// ------------------------------------------------------------------
extern "C" void kernel_launch(void* const* d_in, const int* in_sizes, int n_in,
                              void* d_out, int out_size)
{
    const float* x    = (const float*)d_in[0];   // [2048, 1024]
    const float* wqkv = (const float*)d_in[1];   // [96, 1024]
    const float* ws   = (const float*)d_in[2];   // [32, 4096, 1024]
    const float* w2s  = (const float*)d_in[3];   // [32, 1024, 2048]
    float* y = (float*)d_out;                    // [2048, 1024]

    zero_counts_kernel<<<1, 32>>>();

    dim3 gmix(2, T_TOK / 64);
    mix_gemm_kernel<<<gmix, 256>>>(x, wqkv);

    route_kernel<<<T_TOK / 4, 128>>>();

    build_tiles_kernel<<<1, 32>>>();

    dim3 g1((2 * I_DIM) / BN, MAX_TILES);        // (32, 64)
    moe_gemm_tc_kernel<1><<<g1, NTHREADS>>>(x, ws);

    swiglu_kernel<<<T_TOK * 2, 256>>>();

    dim3 g2(H_DIM / BN, MAX_TILES);              // (8, 64)
    moe_gemm_tc_kernel<2><<<g2, NTHREADS>>>(nullptr, w2s);

    combine_kernel<<<T_TOK, 256>>>(y);
}